// round 11
// baseline (speedup 1.0000x reference)
#include <cuda_runtime.h>
#include <cuda_fp16.h>
#include <cstdint>

#define D  64
#define NA 64
#define MAX_ITEM 100000
#define MAX_BZ   1024

// Scratch tables (allocation-free: __device__ globals)
__device__ __align__(16) __half g_Ph[MAX_BZ * NA];             // fp16 P
__device__ __align__(16) __half g_Qh[(size_t)MAX_ITEM * NA];   // fp16 Qd+bias, L2-resident

// ============================ PTX helpers (sm_80+ baseline) ============================
__device__ __forceinline__ uint32_t smem_u32(const void* p) {
    uint32_t a;
    asm("{ .reg .u64 t; cvta.to.shared.u64 t, %1; cvt.u32.u64 %0, t; }"
        : "=r"(a) : "l"(p));
    return a;
}
__device__ __forceinline__ void ldmatrix_x4(uint32_t& r0, uint32_t& r1,
                                            uint32_t& r2, uint32_t& r3,
                                            uint32_t addr) {
    asm volatile("ldmatrix.sync.aligned.m8n8.x4.shared.b16 {%0,%1,%2,%3}, [%4];"
                 : "=r"(r0), "=r"(r1), "=r"(r2), "=r"(r3) : "r"(addr));
}
__device__ __forceinline__ void mma_16816(float* d, uint32_t a0, uint32_t a1,
                                          uint32_t a2, uint32_t a3,
                                          uint32_t b0, uint32_t b1) {
    asm volatile(
        "mma.sync.aligned.m16n8k16.row.col.f32.f16.f16.f32 "
        "{%0,%1,%2,%3}, {%4,%5,%6,%7}, {%8,%9}, {%0,%1,%2,%3};"
        : "+f"(d[0]), "+f"(d[1]), "+f"(d[2]), "+f"(d[3])
        : "r"(a0), "r"(a1), "r"(a2), "r"(a3), "r"(b0), "r"(b1));
}

// ---------------------------------------------------------------------------
// Qd via HMMA (mma.sync): 128 items/block, 8 warps x 16 items.
// I and A staged fp16 in smem, 128B rows, XOR chunk swizzle (c ^ (row&7)).
// logits[16x64] = I_tile[16x64] @ A[64x64]^T in fp32 accumulators.
// Epilogue: quad owns an item row; en = ep * K_a with K_a = exp(rnA - rpA).
// ---------------------------------------------------------------------------
__global__ void __launch_bounds__(256) qd_mma_kernel(
        const float* __restrict__ Iemb,
        const float* __restrict__ A,
        const float* __restrict__ Rel,
        const float* __restrict__ bias,
        int nitem) {
    __shared__ __align__(16) char I_s[128 * 128];   // 128 items x 64 fp16 (swizzled)
    __shared__ __align__(16) char As [64 * 128];    // 64 aspects x 64 fp16 (swizzled)
    __shared__ float sR[128];                       // [0,64)=rpA, [64,128)=K_a
    __shared__ __align__(16) char stage[128 * 144]; // epilogue staging

    int t = threadIdx.x, w = t >> 5, lane = t & 31;
    int base = blockIdx.x * 128;

    // ---- load + convert I tile (guarded, zero-pad) ----
    {
        const float4* gI = (const float4*)Iemb;
        int lim = nitem * 16;
#pragma unroll
        for (int i = 0; i < 8; i++) {
            int f = t + 256 * i;                    // float4 id in tile (2048 total)
            int row = f >> 4, q = f & 15;
            int gidx = base * 16 + f;
            float4 v = (gidx < lim) ? gI[gidx] : make_float4(0.f, 0.f, 0.f, 0.f);
            int c = q >> 1, sub = q & 1;
            int off = row * 128 + ((c ^ (row & 7)) << 4) + sub * 8;
            __half2 h01 = __floats2half2_rn(v.x, v.y);
            __half2 h23 = __floats2half2_rn(v.z, v.w);
            *(uint2*)(I_s + off) = make_uint2(*(uint32_t*)&h01, *(uint32_t*)&h23);
        }
        // ---- load + convert A tile ----
        const float4* gA = (const float4*)A;
#pragma unroll
        for (int i = 0; i < 4; i++) {
            int f = t + 256 * i;                    // 1024 float4
            int row = f >> 4, q = f & 15;
            float4 v = gA[f];
            int c = q >> 1, sub = q & 1;
            int off = row * 128 + ((c ^ (row & 7)) << 4) + sub * 8;
            __half2 h01 = __floats2half2_rn(v.x, v.y);
            __half2 h23 = __floats2half2_rn(v.z, v.w);
            *(uint2*)(As + off) = make_uint2(*(uint32_t*)&h01, *(uint32_t*)&h23);
        }
    }
    // ---- rpA / rnA from fp32 global (exact, cheap: 128 dots of 64) ----
    if (t < 128) {
        int rr = 1 + (t >> 6), a = t & 63;
        const float* rv = Rel + rr * D;
        const float* ar = A + a * D;
        float s = 0.f;
#pragma unroll
        for (int d = 0; d < 64; d++) s += rv[d] * ar[d];
        sR[t] = s;                                  // [0,64)=rpA, [64,128)=rnA
    }
    __syncthreads();
    if (t < 64) sR[64 + t] = __expf(sR[64 + t] - sR[t]);   // K_a
    __syncthreads();

    // ---- MMA mainloop: warp w -> items [16w, 16w+16) of the block tile ----
    uint32_t iBase = smem_u32(I_s);
    uint32_t aBase = smem_u32(As);
    int item0 = w * 16;
    float acc[8][4];                                // acc[nblock][c0..c3]
#pragma unroll
    for (int nb = 0; nb < 8; nb++)
#pragma unroll
        for (int c = 0; c < 4; c++) acc[nb][c] = 0.f;

#pragma unroll
    for (int ks = 0; ks < 4; ks++) {                // k = 16ks .. 16ks+15
        // A-operand fragment (items x k): 4 tiles (row-lo/hi x k-lo/hi)
        int sel = lane >> 3, r = lane & 7;
        int arow = item0 + r + ((sel & 1) << 3);
        int ach  = 2 * ks + (sel >> 1);
        uint32_t aaddr = iBase + arow * 128 + ((ach ^ (arow & 7)) << 4);
        uint32_t a0, a1, a2, a3;
        ldmatrix_x4(a0, a1, a2, a3, aaddr);

#pragma unroll
        for (int nbp = 0; nbp < 4; nbp++) {         // aspect-block pairs
            int nb  = 2 * nbp + (lane >> 4);
            int bch = 2 * ks + ((lane >> 3) & 1);
            int brow = 8 * nb + (lane & 7);
            uint32_t baddr = aBase + brow * 128 + ((bch ^ (brow & 7)) << 4);
            uint32_t b0, b1, b2, b3;
            ldmatrix_x4(b0, b1, b2, b3, baddr);
            mma_16816(acc[2 * nbp],     a0, a1, a2, a3, b0, b1);
            mma_16816(acc[2 * nbp + 1], a0, a1, a2, a3, b2, b3);
        }
    }

    // ---- epilogue: quad (g = lane>>2) owns items item0+g and item0+g+8 ----
    int g = lane >> 2, tg = lane & 3;
#pragma unroll
    for (int half = 0; half < 2; half++) {
        int locItem = item0 + g + 8 * half;
        int item = base + locItem;
        // this thread's 16 aspects: a = 8nb + 2tg + {0,1}
        float e[8][2], sp = 0.f, sn = 0.f;
#pragma unroll
        for (int nb = 0; nb < 8; nb++) {
            int a = 8 * nb + 2 * tg;
            float L0 = acc[nb][2 * half];
            float L1 = acc[nb][2 * half + 1];
            float e0 = __expf(L0 + sR[a]);
            float e1 = __expf(L1 + sR[a + 1]);
            e[nb][0] = e0; e[nb][1] = e1;
            sp += e0 + e1;
            sn += e0 * sR[64 + a] + e1 * sR[65 + a];
        }
        // quad reduce (xor within quad)
        sp += __shfl_xor_sync(0xffffffffu, sp, 1);
        sp += __shfl_xor_sync(0xffffffffu, sp, 2);
        sn += __shfl_xor_sync(0xffffffffu, sn, 1);
        sn += __shfl_xor_sync(0xffffffffu, sn, 2);
        float isp = __fdividef(1.f, sp);
        float isn = __fdividef(1.f, sn);
        float bb  = bias[item < nitem ? item : (nitem - 1)];
#pragma unroll
        for (int nb = 0; nb < 8; nb++) {
            int a = 8 * nb + 2 * tg;
            float q0 = e[nb][0] * isp - e[nb][0] * sR[64 + a] * isn + bb;
            float q1 = e[nb][1] * isp - e[nb][1] * sR[65 + a] * isn + bb;
            __half2 h = __floats2half2_rn(q0, q1);
            // stage row stride 144B: bank (4*locItem + 4nb + tg) distinct per phase
            *(__half2*)(stage + locItem * 144 + (a << 1)) = h;
        }
    }
    __syncwarp();

    // ---- coalesced copy: warp w stores its 16 rows (16 x 128B) ----
#pragma unroll
    for (int i = 0; i < 4; i++) {
        int idx = lane + 32 * i;                    // 128 chunks of 16B
        int row = idx >> 3, c = idx & 7;
        int item = base + item0 + row;
        if (item < nitem) {
            uint4 v = *(const uint4*)(stage + (item0 + row) * 144 + c * 16);
            ((uint4*)g_Qh)[(size_t)item * 8 + c] = v;
        }
    }
}

// ---------------------------------------------------------------------------
// P: 8 users/block, scalar fp32 -> g_Ph fp16
// ---------------------------------------------------------------------------
__global__ void __launch_bounds__(256) p_kernel(
        const int* __restrict__ uidx,
        const float* __restrict__ Uemb,
        const float* __restrict__ A,
        const float* __restrict__ Rel,
        int bz) {
    __shared__ float A_s[64 * 65];
    __shared__ float sRu[64];
    __shared__ float us[8][64];
    int t = threadIdx.x;
    for (int i = t; i < 64 * 64; i += 256)
        A_s[(i >> 6) * 65 + (i & 63)] = A[i];
    __syncthreads();
    if (t < 64) {
        const float* ar = A_s + t * 65;
        float s = 0.f;
#pragma unroll
        for (int d = 0; d < 64; d++) s += Rel[d] * ar[d];
        sRu[t] = s;
    }
    __syncthreads();

    int w = t >> 5, lane = t & 31;
    int row = blockIdx.x * 8 + w;
    if (row >= bz) return;
    const float* U = Uemb + (size_t)uidx[row] * D;
    ((float2*)us[w])[lane] = ((const float2*)U)[lane];
    __syncwarp();

    const float* Ar0 = A_s + lane * 65;
    const float* Ar1 = A_s + (lane + 32) * 65;
    float acc0 = 0.f, acc1 = 0.f;
#pragma unroll
    for (int d = 0; d < 64; d++) {
        float u = us[w][d];
        acc0 += u * Ar0[d];
        acc1 += u * Ar1[d];
    }
    float l0 = acc0 + sRu[lane], l1 = acc1 + sRu[lane + 32];
    float m = fmaxf(l0, l1);
#pragma unroll
    for (int o = 16; o; o >>= 1) m = fmaxf(m, __shfl_xor_sync(0xffffffffu, m, o));
    float e0 = __expf(l0 - m), e1 = __expf(l1 - m);
    float s = e0 + e1;
#pragma unroll
    for (int o = 16; o; o >>= 1) s += __shfl_xor_sync(0xffffffffu, s, o);
    float inv = __fdividef(1.f, s);
    __half* prow = g_Ph + row * NA;
    prow[lane]      = __float2half_rn(e0 * inv);
    prow[lane + 32] = __float2half_rn(e1 * inv);
}

// ---------------------------------------------------------------------------
// Main (unchanged from passing R10): pipelined gather + all-fp16 dot + softmax.
// ---------------------------------------------------------------------------
__global__ void __launch_bounds__(256) main_kernel(
        const int* __restrict__ iidx,
        float* __restrict__ out, int ns) {
    __shared__ __align__(16) uint4 Psh[8];
    __shared__ __align__(16) float rat[1024];
    __shared__ float red[8];
    int b = blockIdx.x;
    int t = threadIdx.x;
    if (t < 8) Psh[t] = ((const uint4*)(g_Ph + b * 64))[t];
    __syncthreads();

    int w = t >> 5, lane = t & 31, g8 = lane >> 2, q4 = lane & 3;
    uint4 prA = Psh[q4];
    uint4 prB = Psh[q4 + 4];
    __half2 pa0 = *(__half2*)&prA.x, pa1 = *(__half2*)&prA.y;
    __half2 pa2 = *(__half2*)&prA.z, pa3 = *(__half2*)&prA.w;
    __half2 pb0 = *(__half2*)&prB.x, pb1 = *(__half2*)&prB.y;
    __half2 pb2 = *(__half2*)&prB.z, pb3 = *(__half2*)&prB.w;
    const int* idxrow = iidx + (size_t)b * ns;
    int nsp = (ns + 255) & ~255;

    int cidx[4];
    {
        int s0 = w * 32;
#pragma unroll
        for (int k = 0; k < 4; k++) {
            int s = s0 + k * 8 + g8;
            cidx[k] = (s < ns) ? idxrow[s] : 0;
        }
    }

    for (int s0 = w * 32; s0 < nsp; s0 += 256) {
        uint4 ra[4], rb[4];
#pragma unroll
        for (int k = 0; k < 4; k++) {
            const uint4* row = (const uint4*)(g_Qh + (size_t)cidx[k] * NA);
            ra[k] = __ldcg(row + q4);
            rb[k] = __ldcg(row + q4 + 4);
        }
        int nidx[4] = {0, 0, 0, 0};
        int s1 = s0 + 256;
        if (s1 < nsp) {
#pragma unroll
            for (int k = 0; k < 4; k++) {
                int s = s1 + k * 8 + g8;
                nidx[k] = (s < ns) ? idxrow[s] : 0;
            }
        }
#pragma unroll
        for (int k = 0; k < 4; k++) {
            __half2 acc = __hmul2(*(__half2*)&ra[k].x, pa0);
            acc = __hfma2(*(__half2*)&ra[k].y, pa1, acc);
            acc = __hfma2(*(__half2*)&ra[k].z, pa2, acc);
            acc = __hfma2(*(__half2*)&ra[k].w, pa3, acc);
            acc = __hfma2(*(__half2*)&rb[k].x, pb0, acc);
            acc = __hfma2(*(__half2*)&rb[k].y, pb1, acc);
            acc = __hfma2(*(__half2*)&rb[k].z, pb2, acc);
            acc = __hfma2(*(__half2*)&rb[k].w, pb3, acc);
            float2 f = __half22float2(acc);
            float r = f.x + f.y;
            r += __shfl_xor_sync(0xffffffffu, r, 1);
            r += __shfl_xor_sync(0xffffffffu, r, 2);
            int s = s0 + k * 8 + g8;
            if (s < ns && q4 == 0) rat[s] = r;
        }
#pragma unroll
        for (int k = 0; k < 4; k++) cidx[k] = nidx[k];
    }
    __syncthreads();

    float m = -1e30f;
    for (int s = t; s < ns; s += 256) m = fmaxf(m, rat[s]);
#pragma unroll
    for (int o = 16; o; o >>= 1) m = fmaxf(m, __shfl_xor_sync(0xffffffffu, m, o));
    if (lane == 0) red[w] = m;
    __syncthreads();
    if (t == 0) {
        float v = red[0];
#pragma unroll
        for (int i = 1; i < 8; i++) v = fmaxf(v, red[i]);
        red[0] = v;
    }
    __syncthreads();
    m = red[0];
    __syncthreads();

    float sum = 0.f;
    for (int s = t; s < ns; s += 256) {
        float e = __expf(rat[s] - m);
        rat[s] = e;
        sum += e;
    }
#pragma unroll
    for (int o = 16; o; o >>= 1) sum += __shfl_xor_sync(0xffffffffu, sum, o);
    if (lane == 0) red[w] = sum;
    __syncthreads();
    if (t == 0) {
        float v = red[0];
#pragma unroll
        for (int i = 1; i < 8; i++) v += red[i];
        red[0] = v;
    }
    __syncthreads();
    float inv = __fdividef(1.f, red[0]);
    float* orow = out + (size_t)b * ns;
    for (int s = t; s < ns; s += 256) orow[s] = rat[s] * inv;
}

// ---------------------------------------------------------------------------
// Launch
// ---------------------------------------------------------------------------
extern "C" void kernel_launch(void* const* d_in, const int* in_sizes, int n_in,
                              void* d_out, int out_size) {
    const int*   uidx = (const int*)d_in[0];
    const int*   iidx = (const int*)d_in[1];
    const float* Uemb = (const float*)d_in[2];
    const float* Iemb = (const float*)d_in[3];
    const float* A    = (const float*)d_in[4];
    const float* Rel  = (const float*)d_in[5];
    const float* bias = (const float*)d_in[6];
    float* out = (float*)d_out;

    int bz    = in_sizes[0];
    int ns    = in_sizes[1] / bz;
    int nitem = in_sizes[3] / D;

    qd_mma_kernel<<<(nitem + 127) / 128, 256>>>(Iemb, A, Rel, bias, nitem);
    p_kernel<<<(bz + 7) / 8, 256>>>(uidx, Uemb, A, Rel, bz);
    main_kernel<<<bz, 256>>>(iidx, out, ns);
}

// round 13
// speedup vs baseline: 1.5549x; 1.5549x over previous
#include <cuda_runtime.h>
#include <cuda_fp16.h>
#include <cstdint>

#define D  64
#define NA 64
#define MAX_ITEM 100000
#define MAX_BZ   1024

// Scratch tables (allocation-free: __device__ globals)
__device__ __align__(16) __half g_Ph[MAX_BZ * NA];             // fp16 P
__device__ __align__(16) __half g_Qh[(size_t)MAX_ITEM * NA];   // fp16 Qd+bias, L2-resident
__device__ float g_rp[64];                                     // rpA
__device__ float g_K[64];                                      // exp(rnA - rpA)

// ============================ PTX helpers (sm_80+ baseline) ============================
__device__ __forceinline__ uint32_t smem_u32(const void* p) {
    uint32_t a;
    asm("{ .reg .u64 t; cvta.to.shared.u64 t, %1; cvt.u32.u64 %0, t; }"
        : "=r"(a) : "l"(p));
    return a;
}
__device__ __forceinline__ void ldmatrix_x4(uint32_t& r0, uint32_t& r1,
                                            uint32_t& r2, uint32_t& r3,
                                            uint32_t addr) {
    asm volatile("ldmatrix.sync.aligned.m8n8.x4.shared.b16 {%0,%1,%2,%3}, [%4];"
                 : "=r"(r0), "=r"(r1), "=r"(r2), "=r"(r3) : "r"(addr));
}
__device__ __forceinline__ void mma_16816(float* d, uint32_t a0, uint32_t a1,
                                          uint32_t a2, uint32_t a3,
                                          uint32_t b0, uint32_t b1) {
    asm volatile(
        "mma.sync.aligned.m16n8k16.row.col.f32.f16.f16.f32 "
        "{%0,%1,%2,%3}, {%4,%5,%6,%7}, {%8,%9}, {%0,%1,%2,%3};"
        : "+f"(d[0]), "+f"(d[1]), "+f"(d[2]), "+f"(d[3])
        : "r"(a0), "r"(a1), "r"(a2), "r"(a3), "r"(b0), "r"(b1));
}

// ---------------------------------------------------------------------------
// One-shot relation projections: rpA, K = exp(rnA - rpA). 64 threads, 1 block.
// ---------------------------------------------------------------------------
__global__ void relA_kernel(const float* __restrict__ A,
                            const float* __restrict__ Rel) {
    int a = threadIdx.x;                 // 0..63
    const float* rp_ = Rel + 1 * D;      // Rip
    const float* rn_ = Rel + 2 * D;      // Rin
    const float* ar  = A + a * D;
    float sp = 0.f, sn = 0.f;
#pragma unroll
    for (int d = 0; d < 64; d++) {
        float av = ar[d];
        sp += rp_[d] * av;
        sn += rn_[d] * av;
    }
    g_rp[a] = sp;
    g_K[a]  = __expf(sn - sp);
}

// ---------------------------------------------------------------------------
// Qd via HMMA (mma.sync): 128 items/block, 8 warps x 16 items.
// I and A staged fp16 in smem, 128B rows, XOR chunk swizzle (c ^ (row&7)).
// Epilogue staging ALIASES the tile arena (tiles dead after mainloop).
// ---------------------------------------------------------------------------
__global__ void __launch_bounds__(256, 3) qd_mma_kernel(
        const float* __restrict__ Iemb,
        const float* __restrict__ A,
        const float* __restrict__ bias,
        int nitem) {
    __shared__ __align__(16) char arena[128 * 128 + 64 * 128];  // 24 KB
    __shared__ float sR[128];                       // [0,64)=rpA, [64,128)=K_a
    char* I_s   = arena;                            // 128 x 128B (16 KB)
    char* As    = arena + 128 * 128;                // 64 x 128B  (8 KB)
    char* stage = arena;                            // 128 x 144B (18 KB), aliased

    int t = threadIdx.x, w = t >> 5, lane = t & 31;
    int base = blockIdx.x * 128;

    // ---- coalesced load of precomputed projections ----
    if (t < 64) { sR[t] = g_rp[t]; sR[64 + t] = g_K[t]; }

    // ---- load + convert I tile (guarded, zero-pad) ----
    {
        const float4* gI = (const float4*)Iemb;
        int lim = nitem * 16;
#pragma unroll
        for (int i = 0; i < 8; i++) {
            int f = t + 256 * i;                    // float4 id in tile (2048 total)
            int row = f >> 4, q = f & 15;
            int gidx = base * 16 + f;
            float4 v = (gidx < lim) ? gI[gidx] : make_float4(0.f, 0.f, 0.f, 0.f);
            int c = q >> 1, sub = q & 1;
            int off = row * 128 + ((c ^ (row & 7)) << 4) + sub * 8;
            __half2 h01 = __floats2half2_rn(v.x, v.y);
            __half2 h23 = __floats2half2_rn(v.z, v.w);
            *(uint2*)(I_s + off) = make_uint2(*(uint32_t*)&h01, *(uint32_t*)&h23);
        }
        // ---- load + convert A tile ----
        const float4* gA = (const float4*)A;
#pragma unroll
        for (int i = 0; i < 4; i++) {
            int f = t + 256 * i;                    // 1024 float4
            int row = f >> 4, q = f & 15;
            float4 v = gA[f];
            int c = q >> 1, sub = q & 1;
            int off = row * 128 + ((c ^ (row & 7)) << 4) + sub * 8;
            __half2 h01 = __floats2half2_rn(v.x, v.y);
            __half2 h23 = __floats2half2_rn(v.z, v.w);
            *(uint2*)(As + off) = make_uint2(*(uint32_t*)&h01, *(uint32_t*)&h23);
        }
    }
    __syncthreads();

    // ---- MMA mainloop: warp w -> items [16w, 16w+16) of the block tile ----
    uint32_t iBase = smem_u32(I_s);
    uint32_t aBase = smem_u32(As);
    int item0 = w * 16;
    float acc[8][4];                                // acc[nblock][c0..c3]
#pragma unroll
    for (int nb = 0; nb < 8; nb++)
#pragma unroll
        for (int c = 0; c < 4; c++) acc[nb][c] = 0.f;

#pragma unroll
    for (int ks = 0; ks < 4; ks++) {                // k = 16ks .. 16ks+15
        int sel = lane >> 3, r = lane & 7;
        int arow = item0 + r + ((sel & 1) << 3);
        int ach  = 2 * ks + (sel >> 1);
        uint32_t aaddr = iBase + arow * 128 + ((ach ^ (arow & 7)) << 4);
        uint32_t a0, a1, a2, a3;
        ldmatrix_x4(a0, a1, a2, a3, aaddr);

#pragma unroll
        for (int nbp = 0; nbp < 4; nbp++) {         // aspect-block pairs
            int nb  = 2 * nbp + (lane >> 4);
            int bch = 2 * ks + ((lane >> 3) & 1);
            int brow = 8 * nb + (lane & 7);
            uint32_t baddr = aBase + brow * 128 + ((bch ^ (brow & 7)) << 4);
            uint32_t b0, b1, b2, b3;
            ldmatrix_x4(b0, b1, b2, b3, baddr);
            mma_16816(acc[2 * nbp],     a0, a1, a2, a3, b0, b1);
            mma_16816(acc[2 * nbp + 1], a0, a1, a2, a3, b2, b3);
        }
    }
    __syncthreads();   // tiles dead; stage aliases the arena

    // ---- epilogue: quad (g = lane>>2) owns items item0+g and item0+g+8 ----
    int g = lane >> 2, tg = lane & 3;
#pragma unroll
    for (int half = 0; half < 2; half++) {
        int locItem = item0 + g + 8 * half;
        int item = base + locItem;
        float e[8][2], sp = 0.f, sn = 0.f;
#pragma unroll
        for (int nb = 0; nb < 8; nb++) {
            int a = 8 * nb + 2 * tg;
            float L0 = acc[nb][2 * half];
            float L1 = acc[nb][2 * half + 1];
            float e0 = __expf(L0 + sR[a]);
            float e1 = __expf(L1 + sR[a + 1]);
            e[nb][0] = e0; e[nb][1] = e1;
            sp += e0 + e1;
            sn += e0 * sR[64 + a] + e1 * sR[65 + a];
        }
        sp += __shfl_xor_sync(0xffffffffu, sp, 1);
        sp += __shfl_xor_sync(0xffffffffu, sp, 2);
        sn += __shfl_xor_sync(0xffffffffu, sn, 1);
        sn += __shfl_xor_sync(0xffffffffu, sn, 2);
        float isp = __fdividef(1.f, sp);
        float isn = __fdividef(1.f, sn);
        float bb  = bias[item < nitem ? item : (nitem - 1)];
#pragma unroll
        for (int nb = 0; nb < 8; nb++) {
            int a = 8 * nb + 2 * tg;
            float q0 = e[nb][0] * isp - e[nb][0] * sR[64 + a] * isn + bb;
            float q1 = e[nb][1] * isp - e[nb][1] * sR[65 + a] * isn + bb;
            __half2 h = __floats2half2_rn(q0, q1);
            *(__half2*)(stage + locItem * 144 + (a << 1)) = h;
        }
    }
    __syncwarp();

    // ---- coalesced copy: warp w stores its 16 rows (16 x 128B) ----
#pragma unroll
    for (int i = 0; i < 4; i++) {
        int idx = lane + 32 * i;                    // 128 chunks of 16B
        int row = idx >> 3, c = idx & 7;
        int item = base + item0 + row;
        if (item < nitem) {
            uint4 v = *(const uint4*)(stage + (item0 + row) * 144 + c * 16);
            ((uint4*)g_Qh)[(size_t)item * 8 + c] = v;
        }
    }
}

// ---------------------------------------------------------------------------
// P: 8 users/block, scalar fp32 -> g_Ph fp16
// ---------------------------------------------------------------------------
__global__ void __launch_bounds__(256) p_kernel(
        const int* __restrict__ uidx,
        const float* __restrict__ Uemb,
        const float* __restrict__ A,
        const float* __restrict__ Rel,
        int bz) {
    __shared__ float A_s[64 * 65];
    __shared__ float sRu[64];
    __shared__ float us[8][64];
    int t = threadIdx.x;
    for (int i = t; i < 64 * 64; i += 256)
        A_s[(i >> 6) * 65 + (i & 63)] = A[i];
    __syncthreads();
    if (t < 64) {
        const float* ar = A_s + t * 65;
        float s = 0.f;
#pragma unroll
        for (int d = 0; d < 64; d++) s += Rel[d] * ar[d];
        sRu[t] = s;
    }
    __syncthreads();

    int w = t >> 5, lane = t & 31;
    int row = blockIdx.x * 8 + w;
    if (row >= bz) return;
    const float* U = Uemb + (size_t)uidx[row] * D;
    ((float2*)us[w])[lane] = ((const float2*)U)[lane];
    __syncwarp();

    const float* Ar0 = A_s + lane * 65;
    const float* Ar1 = A_s + (lane + 32) * 65;
    float acc0 = 0.f, acc1 = 0.f;
#pragma unroll
    for (int d = 0; d < 64; d++) {
        float u = us[w][d];
        acc0 += u * Ar0[d];
        acc1 += u * Ar1[d];
    }
    float l0 = acc0 + sRu[lane], l1 = acc1 + sRu[lane + 32];
    float m = fmaxf(l0, l1);
#pragma unroll
    for (int o = 16; o; o >>= 1) m = fmaxf(m, __shfl_xor_sync(0xffffffffu, m, o));
    float e0 = __expf(l0 - m), e1 = __expf(l1 - m);
    float s = e0 + e1;
#pragma unroll
    for (int o = 16; o; o >>= 1) s += __shfl_xor_sync(0xffffffffu, s, o);
    float inv = __fdividef(1.f, s);
    __half* prow = g_Ph + row * NA;
    prow[lane]      = __float2half_rn(e0 * inv);
    prow[lane + 32] = __float2half_rn(e1 * inv);
}

// ---------------------------------------------------------------------------
// Main (unchanged from passing R10): pipelined gather + all-fp16 dot + softmax.
// ---------------------------------------------------------------------------
__global__ void __launch_bounds__(256) main_kernel(
        const int* __restrict__ iidx,
        float* __restrict__ out, int ns) {
    __shared__ __align__(16) uint4 Psh[8];
    __shared__ __align__(16) float rat[1024];
    __shared__ float red[8];
    int b = blockIdx.x;
    int t = threadIdx.x;
    if (t < 8) Psh[t] = ((const uint4*)(g_Ph + b * 64))[t];
    __syncthreads();

    int w = t >> 5, lane = t & 31, g8 = lane >> 2, q4 = lane & 3;
    uint4 prA = Psh[q4];
    uint4 prB = Psh[q4 + 4];
    __half2 pa0 = *(__half2*)&prA.x, pa1 = *(__half2*)&prA.y;
    __half2 pa2 = *(__half2*)&prA.z, pa3 = *(__half2*)&prA.w;
    __half2 pb0 = *(__half2*)&prB.x, pb1 = *(__half2*)&prB.y;
    __half2 pb2 = *(__half2*)&prB.z, pb3 = *(__half2*)&prB.w;
    const int* idxrow = iidx + (size_t)b * ns;
    int nsp = (ns + 255) & ~255;

    int cidx[4];
    {
        int s0 = w * 32;
#pragma unroll
        for (int k = 0; k < 4; k++) {
            int s = s0 + k * 8 + g8;
            cidx[k] = (s < ns) ? idxrow[s] : 0;
        }
    }

    for (int s0 = w * 32; s0 < nsp; s0 += 256) {
        uint4 ra[4], rb[4];
#pragma unroll
        for (int k = 0; k < 4; k++) {
            const uint4* row = (const uint4*)(g_Qh + (size_t)cidx[k] * NA);
            ra[k] = __ldcg(row + q4);
            rb[k] = __ldcg(row + q4 + 4);
        }
        int nidx[4] = {0, 0, 0, 0};
        int s1 = s0 + 256;
        if (s1 < nsp) {
#pragma unroll
            for (int k = 0; k < 4; k++) {
                int s = s1 + k * 8 + g8;
                nidx[k] = (s < ns) ? idxrow[s] : 0;
            }
        }
#pragma unroll
        for (int k = 0; k < 4; k++) {
            __half2 acc = __hmul2(*(__half2*)&ra[k].x, pa0);
            acc = __hfma2(*(__half2*)&ra[k].y, pa1, acc);
            acc = __hfma2(*(__half2*)&ra[k].z, pa2, acc);
            acc = __hfma2(*(__half2*)&ra[k].w, pa3, acc);
            acc = __hfma2(*(__half2*)&rb[k].x, pb0, acc);
            acc = __hfma2(*(__half2*)&rb[k].y, pb1, acc);
            acc = __hfma2(*(__half2*)&rb[k].z, pb2, acc);
            acc = __hfma2(*(__half2*)&rb[k].w, pb3, acc);
            float2 f = __half22float2(acc);
            float r = f.x + f.y;
            r += __shfl_xor_sync(0xffffffffu, r, 1);
            r += __shfl_xor_sync(0xffffffffu, r, 2);
            int s = s0 + k * 8 + g8;
            if (s < ns && q4 == 0) rat[s] = r;
        }
#pragma unroll
        for (int k = 0; k < 4; k++) cidx[k] = nidx[k];
    }
    __syncthreads();

    float m = -1e30f;
    for (int s = t; s < ns; s += 256) m = fmaxf(m, rat[s]);
#pragma unroll
    for (int o = 16; o; o >>= 1) m = fmaxf(m, __shfl_xor_sync(0xffffffffu, m, o));
    if (lane == 0) red[w] = m;
    __syncthreads();
    if (t == 0) {
        float v = red[0];
#pragma unroll
        for (int i = 1; i < 8; i++) v = fmaxf(v, red[i]);
        red[0] = v;
    }
    __syncthreads();
    m = red[0];
    __syncthreads();

    float sum = 0.f;
    for (int s = t; s < ns; s += 256) {
        float e = __expf(rat[s] - m);
        rat[s] = e;
        sum += e;
    }
#pragma unroll
    for (int o = 16; o; o >>= 1) sum += __shfl_xor_sync(0xffffffffu, sum, o);
    if (lane == 0) red[w] = sum;
    __syncthreads();
    if (t == 0) {
        float v = red[0];
#pragma unroll
        for (int i = 1; i < 8; i++) v += red[i];
        red[0] = v;
    }
    __syncthreads();
    float inv = __fdividef(1.f, red[0]);
    float* orow = out + (size_t)b * ns;
    for (int s = t; s < ns; s += 256) orow[s] = rat[s] * inv;
}

// ---------------------------------------------------------------------------
// Launch
// ---------------------------------------------------------------------------
extern "C" void kernel_launch(void* const* d_in, const int* in_sizes, int n_in,
                              void* d_out, int out_size) {
    const int*   uidx = (const int*)d_in[0];
    const int*   iidx = (const int*)d_in[1];
    const float* Uemb = (const float*)d_in[2];
    const float* Iemb = (const float*)d_in[3];
    const float* A    = (const float*)d_in[4];
    const float* Rel  = (const float*)d_in[5];
    const float* bias = (const float*)d_in[6];
    float* out = (float*)d_out;

    int bz    = in_sizes[0];
    int ns    = in_sizes[1] / bz;
    int nitem = in_sizes[3] / D;

    relA_kernel<<<1, 64>>>(A, Rel);
    qd_mma_kernel<<<(nitem + 127) / 128, 256>>>(Iemb, A, bias, nitem);
    p_kernel<<<(bz + 7) / 8, 256>>>(uidx, Uemb, A, Rel, bz);
    main_kernel<<<bz, 256>>>(iidx, out, ns);
}

// round 15
// speedup vs baseline: 1.8370x; 1.1814x over previous
#include <cuda_runtime.h>
#include <cuda_fp16.h>
#include <cstdint>

#define D  64
#define NA 64
#define MAX_ITEM 100000
#define MAX_BZ   1024

// Scratch tables (allocation-free: __device__ globals)
__device__ __align__(16) __half g_Ph[MAX_BZ * NA];             // fp16 P
__device__ __align__(16) __half g_Qh[(size_t)MAX_ITEM * NA];   // fp16 Qd+bias, L2-resident

// ============================ PTX helpers (sm_80+ baseline) ============================
__device__ __forceinline__ uint32_t smem_u32(const void* p) {
    uint32_t a;
    asm("{ .reg .u64 t; cvta.to.shared.u64 t, %1; cvt.u32.u64 %0, t; }"
        : "=r"(a) : "l"(p));
    return a;
}
__device__ __forceinline__ void ldmatrix_x4(uint32_t& r0, uint32_t& r1,
                                            uint32_t& r2, uint32_t& r3,
                                            uint32_t addr) {
    asm volatile("ldmatrix.sync.aligned.m8n8.x4.shared.b16 {%0,%1,%2,%3}, [%4];"
                 : "=r"(r0), "=r"(r1), "=r"(r2), "=r"(r3) : "r"(addr));
}
__device__ __forceinline__ void mma_16816(float* d, uint32_t a0, uint32_t a1,
                                          uint32_t a2, uint32_t a3,
                                          uint32_t b0, uint32_t b1) {
    asm volatile(
        "mma.sync.aligned.m16n8k16.row.col.f32.f16.f16.f32 "
        "{%0,%1,%2,%3}, {%4,%5,%6,%7}, {%8,%9}, {%0,%1,%2,%3};"
        : "+f"(d[0]), "+f"(d[1]), "+f"(d[2]), "+f"(d[3])
        : "r"(a0), "r"(a1), "r"(a2), "r"(a3), "r"(b0), "r"(b1));
}

// ---------------------------------------------------------------------------
// Fused prep: blocks [0, QB) = Qd via HMMA; blocks [QB, QB+PB) = P rows.
// Qd path: 128 items/block, fp16 tiles + XOR-chunk swizzle, rp/K computed
// per-block from the STAGED fp16 A tile (cheap LDS, no strided global reads).
// Epilogue staging aliases the tile arena.
// ---------------------------------------------------------------------------
__global__ void __launch_bounds__(256, 3) prep_kernel(
        const int* __restrict__ uidx,
        const float* __restrict__ Uemb,
        const float* __restrict__ Iemb,
        const float* __restrict__ A,
        const float* __restrict__ Rel,
        const float* __restrict__ bias,
        int bz, int nitem, int QB) {
    __shared__ __align__(16) char arena[128 * 128 + 64 * 128];  // 24 KB
    __shared__ float sR[128];
    int t = threadIdx.x, w = t >> 5, lane = t & 31;

    if (blockIdx.x < QB) {
        // =================== Qd (HMMA) path ===================
        char* I_s   = arena;                        // 128 x 128B (16 KB)
        char* As    = arena + 128 * 128;            // 64 x 128B  (8 KB)
        char* stage = arena;                        // 128 x 144B, aliased later
        int base = blockIdx.x * 128;

        // ---- load + convert I tile (guarded, zero-pad) ----
        {
            const float4* gI = (const float4*)Iemb;
            int lim = nitem * 16;
#pragma unroll
            for (int i = 0; i < 8; i++) {
                int f = t + 256 * i;                // float4 id in tile (2048)
                int row = f >> 4, q = f & 15;
                int gidx = base * 16 + f;
                float4 v = (gidx < lim) ? gI[gidx] : make_float4(0.f, 0.f, 0.f, 0.f);
                int c = q >> 1, sub = q & 1;
                int off = row * 128 + ((c ^ (row & 7)) << 4) + sub * 8;
                __half2 h01 = __floats2half2_rn(v.x, v.y);
                __half2 h23 = __floats2half2_rn(v.z, v.w);
                *(uint2*)(I_s + off) = make_uint2(*(uint32_t*)&h01, *(uint32_t*)&h23);
            }
            const float4* gA = (const float4*)A;
#pragma unroll
            for (int i = 0; i < 4; i++) {
                int f = t + 256 * i;                // 1024 float4
                int row = f >> 4, q = f & 15;
                float4 v = gA[f];
                int c = q >> 1, sub = q & 1;
                int off = row * 128 + ((c ^ (row & 7)) << 4) + sub * 8;
                __half2 h01 = __floats2half2_rn(v.x, v.y);
                __half2 h23 = __floats2half2_rn(v.z, v.w);
                *(uint2*)(As + off) = make_uint2(*(uint32_t*)&h01, *(uint32_t*)&h23);
            }
        }
        __syncthreads();

        // ---- rp/K from the STAGED fp16 A tile (replaces relA kernel) ----
        if (t < 128) {
            int a = t & 63, rr = t >> 6;            // rr: 0 = Rip, 1 = Rin
            const float* rv = Rel + (1 + rr) * D;
            float s = 0.f;
#pragma unroll
            for (int j = 0; j < 8; j++) {
                const __half2* hp =
                    (const __half2*)(As + a * 128 + ((j ^ (a & 7)) << 4));
#pragma unroll
                for (int u = 0; u < 4; u++) {
                    float2 f = __half22float2(hp[u]);
                    s += rv[j * 8 + 2 * u] * f.x + rv[j * 8 + 2 * u + 1] * f.y;
                }
            }
            sR[rr * 64 + a] = s;                    // [0,64)=rpA, [64,128)=rnA
        }
        __syncthreads();
        if (t < 64) sR[64 + t] = __expf(sR[64 + t] - sR[t]);   // K_a
        __syncthreads();

        // ---- MMA mainloop: warp w -> items [16w, 16w+16) ----
        uint32_t iBase = smem_u32(I_s);
        uint32_t aBase = smem_u32(As);
        int item0 = w * 16;
        float acc[8][4];
#pragma unroll
        for (int nb = 0; nb < 8; nb++)
#pragma unroll
            for (int c = 0; c < 4; c++) acc[nb][c] = 0.f;

#pragma unroll
        for (int ks = 0; ks < 4; ks++) {
            int sel = lane >> 3, r = lane & 7;
            int arow = item0 + r + ((sel & 1) << 3);
            int ach  = 2 * ks + (sel >> 1);
            uint32_t aaddr = iBase + arow * 128 + ((ach ^ (arow & 7)) << 4);
            uint32_t a0, a1, a2, a3;
            ldmatrix_x4(a0, a1, a2, a3, aaddr);
#pragma unroll
            for (int nbp = 0; nbp < 4; nbp++) {
                int nb  = 2 * nbp + (lane >> 4);
                int bch = 2 * ks + ((lane >> 3) & 1);
                int brow = 8 * nb + (lane & 7);
                uint32_t baddr = aBase + brow * 128 + ((bch ^ (brow & 7)) << 4);
                uint32_t b0, b1, b2, b3;
                ldmatrix_x4(b0, b1, b2, b3, baddr);
                mma_16816(acc[2 * nbp],     a0, a1, a2, a3, b0, b1);
                mma_16816(acc[2 * nbp + 1], a0, a1, a2, a3, b2, b3);
            }
        }
        __syncthreads();   // tiles dead; stage aliases the arena

        // ---- epilogue: quad (g) owns items item0+g, item0+g+8 ----
        int g = lane >> 2, tg = lane & 3;
#pragma unroll
        for (int half = 0; half < 2; half++) {
            int locItem = item0 + g + 8 * half;
            int item = base + locItem;
            float e[8][2], sp = 0.f, sn = 0.f;
#pragma unroll
            for (int nb = 0; nb < 8; nb++) {
                int a = 8 * nb + 2 * tg;
                float e0 = __expf(acc[nb][2 * half]     + sR[a]);
                float e1 = __expf(acc[nb][2 * half + 1] + sR[a + 1]);
                e[nb][0] = e0; e[nb][1] = e1;
                sp += e0 + e1;
                sn += e0 * sR[64 + a] + e1 * sR[65 + a];
            }
            sp += __shfl_xor_sync(0xffffffffu, sp, 1);
            sp += __shfl_xor_sync(0xffffffffu, sp, 2);
            sn += __shfl_xor_sync(0xffffffffu, sn, 1);
            sn += __shfl_xor_sync(0xffffffffu, sn, 2);
            float isp = __fdividef(1.f, sp);
            float isn = __fdividef(1.f, sn);
            float bb  = bias[item < nitem ? item : (nitem - 1)];
#pragma unroll
            for (int nb = 0; nb < 8; nb++) {
                int a = 8 * nb + 2 * tg;
                float q0 = e[nb][0] * isp - e[nb][0] * sR[64 + a] * isn + bb;
                float q1 = e[nb][1] * isp - e[nb][1] * sR[65 + a] * isn + bb;
                __half2 h = __floats2half2_rn(q0, q1);
                *(__half2*)(stage + locItem * 144 + (a << 1)) = h;
            }
        }
        __syncwarp();

        // ---- coalesced copy: warp w stores its 16 rows ----
#pragma unroll
        for (int i = 0; i < 4; i++) {
            int idx = lane + 32 * i;
            int row = idx >> 3, c = idx & 7;
            int item = base + item0 + row;
            if (item < nitem) {
                uint4 v = *(const uint4*)(stage + (item0 + row) * 144 + c * 16);
                ((uint4*)g_Qh)[(size_t)item * 8 + c] = v;
            }
        }
    } else {
        // =================== P path: 8 users/block ===================
        float* A_s = (float*)arena;                 // 64*65 floats = 16.6 KB
        float* us  = (float*)(arena + 64 * 65 * 4); // 8*64 floats
        for (int i = t; i < 64 * 64; i += 256)
            A_s[(i >> 6) * 65 + (i & 63)] = A[i];
        __syncthreads();
        if (t < 64) {
            const float* ar = A_s + t * 65;
            float s = 0.f;
#pragma unroll
            for (int d = 0; d < 64; d++) s += Rel[d] * ar[d];
            sR[t] = s;                              // RuA
        }
        __syncthreads();

        int row = (blockIdx.x - QB) * 8 + w;
        if (row >= bz) return;
        const float* U = Uemb + (size_t)uidx[row] * D;
        ((float2*)(us + w * 64))[lane] = ((const float2*)U)[lane];
        __syncwarp();

        const float* Ar0 = A_s + lane * 65;
        const float* Ar1 = A_s + (lane + 32) * 65;
        float acc0 = 0.f, acc1 = 0.f;
#pragma unroll
        for (int d = 0; d < 64; d++) {
            float u = us[w * 64 + d];
            acc0 += u * Ar0[d];
            acc1 += u * Ar1[d];
        }
        float l0 = acc0 + sR[lane], l1 = acc1 + sR[lane + 32];
        float m = fmaxf(l0, l1);
#pragma unroll
        for (int o = 16; o; o >>= 1) m = fmaxf(m, __shfl_xor_sync(0xffffffffu, m, o));
        float e0 = __expf(l0 - m), e1 = __expf(l1 - m);
        float s = e0 + e1;
#pragma unroll
        for (int o = 16; o; o >>= 1) s += __shfl_xor_sync(0xffffffffu, s, o);
        float inv = __fdividef(1.f, s);
        __half* prow = g_Ph + row * NA;
        prow[lane]      = __float2half_rn(e0 * inv);
        prow[lane + 32] = __float2half_rn(e1 * inv);
    }
}

// ---------------------------------------------------------------------------
// Main: pipelined gather + all-fp16 dot; register-tracked max (no rat max scan).
// ---------------------------------------------------------------------------
__global__ void __launch_bounds__(256) main_kernel(
        const int* __restrict__ iidx,
        float* __restrict__ out, int ns) {
    __shared__ __align__(16) uint4 Psh[8];
    __shared__ __align__(16) float rat[1024];
    __shared__ float red[8];
    int b = blockIdx.x;
    int t = threadIdx.x;
    if (t < 8) Psh[t] = ((const uint4*)(g_Ph + b * 64))[t];
    __syncthreads();

    int w = t >> 5, lane = t & 31, g8 = lane >> 2, q4 = lane & 3;
    uint4 prA = Psh[q4];
    uint4 prB = Psh[q4 + 4];
    __half2 pa0 = *(__half2*)&prA.x, pa1 = *(__half2*)&prA.y;
    __half2 pa2 = *(__half2*)&prA.z, pa3 = *(__half2*)&prA.w;
    __half2 pb0 = *(__half2*)&prB.x, pb1 = *(__half2*)&prB.y;
    __half2 pb2 = *(__half2*)&prB.z, pb3 = *(__half2*)&prB.w;
    const int* idxrow = iidx + (size_t)b * ns;
    int nsp = (ns + 255) & ~255;

    int cidx[4];
    {
        int s0 = w * 32;
#pragma unroll
        for (int k = 0; k < 4; k++) {
            int s = s0 + k * 8 + g8;
            cidx[k] = (s < ns) ? idxrow[s] : 0;
        }
    }

    float mloc = -1e30f;   // running max (padded samples use item-0 ratings: a
                           // valid shift — softmax is shift-invariant)
    for (int s0 = w * 32; s0 < nsp; s0 += 256) {
        uint4 ra[4], rb[4];
#pragma unroll
        for (int k = 0; k < 4; k++) {
            const uint4* row = (const uint4*)(g_Qh + (size_t)cidx[k] * NA);
            ra[k] = __ldcg(row + q4);
            rb[k] = __ldcg(row + q4 + 4);
        }
        int nidx[4] = {0, 0, 0, 0};
        int s1 = s0 + 256;
        if (s1 < nsp) {
#pragma unroll
            for (int k = 0; k < 4; k++) {
                int s = s1 + k * 8 + g8;
                nidx[k] = (s < ns) ? idxrow[s] : 0;
            }
        }
#pragma unroll
        for (int k = 0; k < 4; k++) {
            __half2 acc = __hmul2(*(__half2*)&ra[k].x, pa0);
            acc = __hfma2(*(__half2*)&ra[k].y, pa1, acc);
            acc = __hfma2(*(__half2*)&ra[k].z, pa2, acc);
            acc = __hfma2(*(__half2*)&ra[k].w, pa3, acc);
            acc = __hfma2(*(__half2*)&rb[k].x, pb0, acc);
            acc = __hfma2(*(__half2*)&rb[k].y, pb1, acc);
            acc = __hfma2(*(__half2*)&rb[k].z, pb2, acc);
            acc = __hfma2(*(__half2*)&rb[k].w, pb3, acc);
            float2 f = __half22float2(acc);
            float r = f.x + f.y;
            r += __shfl_xor_sync(0xffffffffu, r, 1);
            r += __shfl_xor_sync(0xffffffffu, r, 2);
            mloc = fmaxf(mloc, r);
            int s = s0 + k * 8 + g8;
            if (s < ns && q4 == 0) rat[s] = r;
        }
#pragma unroll
        for (int k = 0; k < 4; k++) cidx[k] = nidx[k];
    }
    // warp max (no rat re-scan)
#pragma unroll
    for (int o = 16; o; o >>= 1)
        mloc = fmaxf(mloc, __shfl_xor_sync(0xffffffffu, mloc, o));
    if (lane == 0) red[w] = mloc;
    __syncthreads();       // also publishes rat[]
    if (t == 0) {
        float v = red[0];
#pragma unroll
        for (int i = 1; i < 8; i++) v = fmaxf(v, red[i]);
        red[0] = v;
    }
    __syncthreads();
    float m = red[0];
    __syncthreads();       // protect red[] before sum phase reuses it

    float sum = 0.f;
    for (int s = t; s < ns; s += 256) {
        float e = __expf(rat[s] - m);
        rat[s] = e;
        sum += e;
    }
#pragma unroll
    for (int o = 16; o; o >>= 1) sum += __shfl_xor_sync(0xffffffffu, sum, o);
    if (lane == 0) red[w] = sum;
    __syncthreads();
    if (t == 0) {
        float v = red[0];
#pragma unroll
        for (int i = 1; i < 8; i++) v += red[i];
        red[0] = v;
    }
    __syncthreads();
    float inv = __fdividef(1.f, red[0]);
    float* orow = out + (size_t)b * ns;
    for (int s = t; s < ns; s += 256) orow[s] = rat[s] * inv;
}

// ---------------------------------------------------------------------------
// Launch: 2 kernels total.
// ---------------------------------------------------------------------------
extern "C" void kernel_launch(void* const* d_in, const int* in_sizes, int n_in,
                              void* d_out, int out_size) {
    const int*   uidx = (const int*)d_in[0];
    const int*   iidx = (const int*)d_in[1];
    const float* Uemb = (const float*)d_in[2];
    const float* Iemb = (const float*)d_in[3];
    const float* A    = (const float*)d_in[4];
    const float* Rel  = (const float*)d_in[5];
    const float* bias = (const float*)d_in[6];
    float* out = (float*)d_out;

    int bz    = in_sizes[0];
    int ns    = in_sizes[1] / bz;
    int nitem = in_sizes[3] / D;

    int QB = (nitem + 127) / 128;
    int PB = (bz + 7) / 8;

    prep_kernel<<<QB + PB, 256>>>(uidx, Uemb, Iemb, A, Rel, bias, bz, nitem, QB);
    main_kernel<<<bz, 256>>>(iidx, out, ns);
}

// round 16
// speedup vs baseline: 1.9109x; 1.0402x over previous
#include <cuda_runtime.h>
#include <cuda_fp16.h>
#include <cstdint>

#define D  64
#define NA 64
#define MAX_ITEM 100000
#define MAX_BZ   1024

// Scratch tables (allocation-free: __device__ globals)
__device__ __align__(16) __half g_Ph[MAX_BZ * NA];             // fp16 P
__device__ __align__(16) __half g_Qh[(size_t)MAX_ITEM * NA];   // fp16 Qd+bias, L2-resident

// ============================ PTX helpers (sm_80+ baseline) ============================
__device__ __forceinline__ uint32_t smem_u32(const void* p) {
    uint32_t a;
    asm("{ .reg .u64 t; cvta.to.shared.u64 t, %1; cvt.u32.u64 %0, t; }"
        : "=r"(a) : "l"(p));
    return a;
}
__device__ __forceinline__ void ldmatrix_x4(uint32_t& r0, uint32_t& r1,
                                            uint32_t& r2, uint32_t& r3,
                                            uint32_t addr) {
    asm volatile("ldmatrix.sync.aligned.m8n8.x4.shared.b16 {%0,%1,%2,%3}, [%4];"
                 : "=r"(r0), "=r"(r1), "=r"(r2), "=r"(r3) : "r"(addr));
}
__device__ __forceinline__ void mma_16816(float* d, uint32_t a0, uint32_t a1,
                                          uint32_t a2, uint32_t a3,
                                          uint32_t b0, uint32_t b1) {
    asm volatile(
        "mma.sync.aligned.m16n8k16.row.col.f32.f16.f16.f32 "
        "{%0,%1,%2,%3}, {%4,%5,%6,%7}, {%8,%9}, {%0,%1,%2,%3};"
        : "+f"(d[0]), "+f"(d[1]), "+f"(d[2]), "+f"(d[3])
        : "r"(a0), "r"(a1), "r"(a2), "r"(a3), "r"(b0), "r"(b1));
}

// ---------------------------------------------------------------------------
// Fused prep (identical to passing R15): blocks [0, QB) = Qd via HMMA;
// blocks [QB, QB+PB) = P rows.
// ---------------------------------------------------------------------------
__global__ void __launch_bounds__(256, 3) prep_kernel(
        const int* __restrict__ uidx,
        const float* __restrict__ Uemb,
        const float* __restrict__ Iemb,
        const float* __restrict__ A,
        const float* __restrict__ Rel,
        const float* __restrict__ bias,
        int bz, int nitem, int QB) {
    __shared__ __align__(16) char arena[128 * 128 + 64 * 128];  // 24 KB
    __shared__ float sR[128];
    int t = threadIdx.x, w = t >> 5, lane = t & 31;

    if (blockIdx.x < QB) {
        // =================== Qd (HMMA) path ===================
        char* I_s   = arena;                        // 128 x 128B (16 KB)
        char* As    = arena + 128 * 128;            // 64 x 128B  (8 KB)
        char* stage = arena;                        // 128 x 144B, aliased later
        int base = blockIdx.x * 128;

        // ---- load + convert I tile (guarded, zero-pad) ----
        {
            const float4* gI = (const float4*)Iemb;
            int lim = nitem * 16;
#pragma unroll
            for (int i = 0; i < 8; i++) {
                int f = t + 256 * i;                // float4 id in tile (2048)
                int row = f >> 4, q = f & 15;
                int gidx = base * 16 + f;
                float4 v = (gidx < lim) ? gI[gidx] : make_float4(0.f, 0.f, 0.f, 0.f);
                int c = q >> 1, sub = q & 1;
                int off = row * 128 + ((c ^ (row & 7)) << 4) + sub * 8;
                __half2 h01 = __floats2half2_rn(v.x, v.y);
                __half2 h23 = __floats2half2_rn(v.z, v.w);
                *(uint2*)(I_s + off) = make_uint2(*(uint32_t*)&h01, *(uint32_t*)&h23);
            }
            const float4* gA = (const float4*)A;
#pragma unroll
            for (int i = 0; i < 4; i++) {
                int f = t + 256 * i;                // 1024 float4
                int row = f >> 4, q = f & 15;
                float4 v = gA[f];
                int c = q >> 1, sub = q & 1;
                int off = row * 128 + ((c ^ (row & 7)) << 4) + sub * 8;
                __half2 h01 = __floats2half2_rn(v.x, v.y);
                __half2 h23 = __floats2half2_rn(v.z, v.w);
                *(uint2*)(As + off) = make_uint2(*(uint32_t*)&h01, *(uint32_t*)&h23);
            }
        }
        __syncthreads();

        // ---- rp/K from the STAGED fp16 A tile ----
        if (t < 128) {
            int a = t & 63, rr = t >> 6;            // rr: 0 = Rip, 1 = Rin
            const float* rv = Rel + (1 + rr) * D;
            float s = 0.f;
#pragma unroll
            for (int j = 0; j < 8; j++) {
                const __half2* hp =
                    (const __half2*)(As + a * 128 + ((j ^ (a & 7)) << 4));
#pragma unroll
                for (int u = 0; u < 4; u++) {
                    float2 f = __half22float2(hp[u]);
                    s += rv[j * 8 + 2 * u] * f.x + rv[j * 8 + 2 * u + 1] * f.y;
                }
            }
            sR[rr * 64 + a] = s;                    // [0,64)=rpA, [64,128)=rnA
        }
        __syncthreads();
        if (t < 64) sR[64 + t] = __expf(sR[64 + t] - sR[t]);   // K_a
        __syncthreads();

        // ---- MMA mainloop: warp w -> items [16w, 16w+16) ----
        uint32_t iBase = smem_u32(I_s);
        uint32_t aBase = smem_u32(As);
        int item0 = w * 16;
        float acc[8][4];
#pragma unroll
        for (int nb = 0; nb < 8; nb++)
#pragma unroll
            for (int c = 0; c < 4; c++) acc[nb][c] = 0.f;

#pragma unroll
        for (int ks = 0; ks < 4; ks++) {
            int sel = lane >> 3, r = lane & 7;
            int arow = item0 + r + ((sel & 1) << 3);
            int ach  = 2 * ks + (sel >> 1);
            uint32_t aaddr = iBase + arow * 128 + ((ach ^ (arow & 7)) << 4);
            uint32_t a0, a1, a2, a3;
            ldmatrix_x4(a0, a1, a2, a3, aaddr);
#pragma unroll
            for (int nbp = 0; nbp < 4; nbp++) {
                int nb  = 2 * nbp + (lane >> 4);
                int bch = 2 * ks + ((lane >> 3) & 1);
                int brow = 8 * nb + (lane & 7);
                uint32_t baddr = aBase + brow * 128 + ((bch ^ (brow & 7)) << 4);
                uint32_t b0, b1, b2, b3;
                ldmatrix_x4(b0, b1, b2, b3, baddr);
                mma_16816(acc[2 * nbp],     a0, a1, a2, a3, b0, b1);
                mma_16816(acc[2 * nbp + 1], a0, a1, a2, a3, b2, b3);
            }
        }
        __syncthreads();   // tiles dead; stage aliases the arena

        // ---- epilogue: quad (g) owns items item0+g, item0+g+8 ----
        int g = lane >> 2, tg = lane & 3;
#pragma unroll
        for (int half = 0; half < 2; half++) {
            int locItem = item0 + g + 8 * half;
            int item = base + locItem;
            float e[8][2], sp = 0.f, sn = 0.f;
#pragma unroll
            for (int nb = 0; nb < 8; nb++) {
                int a = 8 * nb + 2 * tg;
                float e0 = __expf(acc[nb][2 * half]     + sR[a]);
                float e1 = __expf(acc[nb][2 * half + 1] + sR[a + 1]);
                e[nb][0] = e0; e[nb][1] = e1;
                sp += e0 + e1;
                sn += e0 * sR[64 + a] + e1 * sR[65 + a];
            }
            sp += __shfl_xor_sync(0xffffffffu, sp, 1);
            sp += __shfl_xor_sync(0xffffffffu, sp, 2);
            sn += __shfl_xor_sync(0xffffffffu, sn, 1);
            sn += __shfl_xor_sync(0xffffffffu, sn, 2);
            float isp = __fdividef(1.f, sp);
            float isn = __fdividef(1.f, sn);
            float bb  = bias[item < nitem ? item : (nitem - 1)];
#pragma unroll
            for (int nb = 0; nb < 8; nb++) {
                int a = 8 * nb + 2 * tg;
                float q0 = e[nb][0] * isp - e[nb][0] * sR[64 + a] * isn + bb;
                float q1 = e[nb][1] * isp - e[nb][1] * sR[65 + a] * isn + bb;
                __half2 h = __floats2half2_rn(q0, q1);
                *(__half2*)(stage + locItem * 144 + (a << 1)) = h;
            }
        }
        __syncwarp();

        // ---- coalesced copy: warp w stores its 16 rows ----
#pragma unroll
        for (int i = 0; i < 4; i++) {
            int idx = lane + 32 * i;
            int row = idx >> 3, c = idx & 7;
            int item = base + item0 + row;
            if (item < nitem) {
                uint4 v = *(const uint4*)(stage + (item0 + row) * 144 + c * 16);
                ((uint4*)g_Qh)[(size_t)item * 8 + c] = v;
            }
        }
    } else {
        // =================== P path: 8 users/block ===================
        float* A_s = (float*)arena;                 // 64*65 floats = 16.6 KB
        float* us  = (float*)(arena + 64 * 65 * 4); // 8*64 floats
        for (int i = t; i < 64 * 64; i += 256)
            A_s[(i >> 6) * 65 + (i & 63)] = A[i];
        __syncthreads();
        if (t < 64) {
            const float* ar = A_s + t * 65;
            float s = 0.f;
#pragma unroll
            for (int d = 0; d < 64; d++) s += Rel[d] * ar[d];
            sR[t] = s;                              // RuA
        }
        __syncthreads();

        int row = (blockIdx.x - QB) * 8 + w;
        if (row >= bz) return;
        const float* U = Uemb + (size_t)uidx[row] * D;
        ((float2*)(us + w * 64))[lane] = ((const float2*)U)[lane];
        __syncwarp();

        const float* Ar0 = A_s + lane * 65;
        const float* Ar1 = A_s + (lane + 32) * 65;
        float acc0 = 0.f, acc1 = 0.f;
#pragma unroll
        for (int d = 0; d < 64; d++) {
            float u = us[w * 64 + d];
            acc0 += u * Ar0[d];
            acc1 += u * Ar1[d];
        }
        float l0 = acc0 + sR[lane], l1 = acc1 + sR[lane + 32];
        float m = fmaxf(l0, l1);
#pragma unroll
        for (int o = 16; o; o >>= 1) m = fmaxf(m, __shfl_xor_sync(0xffffffffu, m, o));
        float e0 = __expf(l0 - m), e1 = __expf(l1 - m);
        float s = e0 + e1;
#pragma unroll
        for (int o = 16; o; o >>= 1) s += __shfl_xor_sync(0xffffffffu, s, o);
        float inv = __fdividef(1.f, s);
        __half* prow = g_Ph + row * NA;
        prow[lane]      = __float2half_rn(e0 * inv);
        prow[lane + 32] = __float2half_rn(e1 * inv);
    }
}

// ---------------------------------------------------------------------------
// Main: pipelined gather + all-fp16 dot; SHIFT-FREE softmax.
// |r| = |P.(Qp-Qn)+bias| <= ~2.2 (P on simplex, |Qd|<=2) -> exp(r) fp32-safe.
// exp fused into gather loop: e stored to rat, sum accumulated in registers.
// One post-pass (scaled float4 store). No max phase, no separate sum pass.
// ---------------------------------------------------------------------------
__global__ void __launch_bounds__(256) main_kernel(
        const int* __restrict__ iidx,
        float* __restrict__ out, int ns) {
    __shared__ __align__(16) uint4 Psh[8];
    __shared__ __align__(16) float rat[1024];   // exp(r) values
    __shared__ float red[8];
    int b = blockIdx.x;
    int t = threadIdx.x;
    if (t < 8) Psh[t] = ((const uint4*)(g_Ph + b * 64))[t];
    __syncthreads();

    int w = t >> 5, lane = t & 31, g8 = lane >> 2, q4 = lane & 3;
    uint4 prA = Psh[q4];
    uint4 prB = Psh[q4 + 4];
    __half2 pa0 = *(__half2*)&prA.x, pa1 = *(__half2*)&prA.y;
    __half2 pa2 = *(__half2*)&prA.z, pa3 = *(__half2*)&prA.w;
    __half2 pb0 = *(__half2*)&prB.x, pb1 = *(__half2*)&prB.y;
    __half2 pb2 = *(__half2*)&prB.z, pb3 = *(__half2*)&prB.w;
    const int* idxrow = iidx + (size_t)b * ns;
    int nsp = (ns + 255) & ~255;

    int cidx[4];
    {
        int s0 = w * 32;
#pragma unroll
        for (int k = 0; k < 4; k++) {
            int s = s0 + k * 8 + g8;
            cidx[k] = (s < ns) ? idxrow[s] : 0;
        }
    }

    float psum = 0.f;                   // per-thread partial sum of exp(r)
    for (int s0 = w * 32; s0 < nsp; s0 += 256) {
        uint4 ra[4], rb[4];
#pragma unroll
        for (int k = 0; k < 4; k++) {
            const uint4* row = (const uint4*)(g_Qh + (size_t)cidx[k] * NA);
            ra[k] = __ldcg(row + q4);
            rb[k] = __ldcg(row + q4 + 4);
        }
        int nidx[4] = {0, 0, 0, 0};
        int s1 = s0 + 256;
        if (s1 < nsp) {
#pragma unroll
            for (int k = 0; k < 4; k++) {
                int s = s1 + k * 8 + g8;
                nidx[k] = (s < ns) ? idxrow[s] : 0;
            }
        }
#pragma unroll
        for (int k = 0; k < 4; k++) {
            __half2 acc = __hmul2(*(__half2*)&ra[k].x, pa0);
            acc = __hfma2(*(__half2*)&ra[k].y, pa1, acc);
            acc = __hfma2(*(__half2*)&ra[k].z, pa2, acc);
            acc = __hfma2(*(__half2*)&ra[k].w, pa3, acc);
            acc = __hfma2(*(__half2*)&rb[k].x, pb0, acc);
            acc = __hfma2(*(__half2*)&rb[k].y, pb1, acc);
            acc = __hfma2(*(__half2*)&rb[k].z, pb2, acc);
            acc = __hfma2(*(__half2*)&rb[k].w, pb3, acc);
            float2 f = __half22float2(acc);
            float r = f.x + f.y;
            r += __shfl_xor_sync(0xffffffffu, r, 1);
            r += __shfl_xor_sync(0xffffffffu, r, 2);
            int s = s0 + k * 8 + g8;
            if (s < ns && q4 == 0) {
                float e = __expf(r);    // shift-free: |r| <= ~2.2
                psum += e;
                rat[s] = e;
            }
        }
#pragma unroll
        for (int k = 0; k < 4; k++) cidx[k] = nidx[k];
    }
    // block sum of exp
#pragma unroll
    for (int o = 16; o; o >>= 1) psum += __shfl_xor_sync(0xffffffffu, psum, o);
    if (lane == 0) red[w] = psum;
    __syncthreads();        // also publishes rat[]
    if (t == 0) {
        float v = red[0];
#pragma unroll
        for (int i = 1; i < 8; i++) v += red[i];
        red[0] = v;
    }
    __syncthreads();
    float inv = __fdividef(1.f, red[0]);

    // scaled store (vectorized when rows are 16B-aligned)
    float* orow = out + (size_t)b * ns;
    if ((ns & 3) == 0) {
        float4* rat4 = (float4*)rat;
        float4* out4 = (float4*)orow;
        int nv4 = ns >> 2;
        for (int i = t; i < nv4; i += 256) {
            float4 v = rat4[i];
            v.x *= inv; v.y *= inv; v.z *= inv; v.w *= inv;
            out4[i] = v;
        }
    } else {
        for (int s = t; s < ns; s += 256) orow[s] = rat[s] * inv;
    }
}

// ---------------------------------------------------------------------------
// Launch: 2 kernels total.
// ---------------------------------------------------------------------------
extern "C" void kernel_launch(void* const* d_in, const int* in_sizes, int n_in,
                              void* d_out, int out_size) {
    const int*   uidx = (const int*)d_in[0];
    const int*   iidx = (const int*)d_in[1];
    const float* Uemb = (const float*)d_in[2];
    const float* Iemb = (const float*)d_in[3];
    const float* A    = (const float*)d_in[4];
    const float* Rel  = (const float*)d_in[5];
    const float* bias = (const float*)d_in[6];
    float* out = (float*)d_out;

    int bz    = in_sizes[0];
    int ns    = in_sizes[1] / bz;
    int nitem = in_sizes[3] / D;

    int QB = (nitem + 127) / 128;
    int PB = (bz + 7) / 8;

    prep_kernel<<<QB + PB, 256>>>(uidx, Uemb, Iemb, A, Rel, bias, bz, nitem, QB);
    main_kernel<<<bz, 256>>>(iidx, out, ns);
}